// round 1
// baseline (speedup 1.0000x reference)
#include <cuda_runtime.h>
#include <math.h>
#include <stdint.h>

#define NB 8
#define HH 128
#define WW 128
#define NC 192
#define C3 576
#define HEADS 4
#define CH 48          // channels per head
#define HW 16384       // H*W
#define BNT 32         // NB*HEADS

// ---------------- scratch (device globals; no allocation allowed) ----------------
__device__ float g_qkv[(size_t)NB * HW * C3];   // 288 MiB
__device__ float g_q[(size_t)NB * HW * NC];     // 96 MiB
__device__ float g_k[(size_t)NB * HW * NC];
__device__ float g_v[(size_t)NB * HW * NC];
__device__ float g_o[(size_t)NB * HW * NC];
__device__ float g_attn[BNT * CH * CH];
__device__ float g_invq[BNT * CH];
__device__ float g_invk[BNT * CH];

// ---------------- generic SGEMM: [M,192] x [192,N] -> [M,N] ----------------
// BM=128, BN=64, BK=16, TM=8, TN=4, 256 threads. M%128==0, N%64==0 assumed.
__global__ __launch_bounds__(256) void sgemm_k192(
    const float* __restrict__ A, const float* __restrict__ Bw,
    float* __restrict__ Cout, int N)
{
    const int K = 192;
    __shared__ float As[16][132];   // padded to dodge store conflicts; 132%4==0 keeps f4 reads aligned
    __shared__ float Bs[16][64];

    int m0 = blockIdx.x * 128;
    int n0 = blockIdx.y * 64;
    int t  = threadIdx.x;
    int tx = t & 15;      // N direction
    int ty = t >> 4;      // M direction

    float acc[8][4];
#pragma unroll
    for (int i = 0; i < 8; i++)
#pragma unroll
        for (int j = 0; j < 4; j++) acc[i][j] = 0.f;

    for (int k0 = 0; k0 < K; k0 += 16) {
        // A tile: 128x16 -> 512 float4, 2 per thread, stored transposed
#pragma unroll
        for (int i = 0; i < 2; i++) {
            int fidx = t + 256 * i;
            int row  = fidx >> 2;      // 0..127
            int c4   = fidx & 3;       // 0..3
            float4 av = *(const float4*)(A + (size_t)(m0 + row) * K + k0 + c4 * 4);
            As[c4 * 4 + 0][row] = av.x;
            As[c4 * 4 + 1][row] = av.y;
            As[c4 * 4 + 2][row] = av.z;
            As[c4 * 4 + 3][row] = av.w;
        }
        // B tile: 16x64 -> 256 float4, 1 per thread
        {
            int row = t >> 4;          // 0..15
            int c4  = t & 15;          // 0..15
            *(float4*)&Bs[row][c4 * 4] =
                *(const float4*)(Bw + (size_t)(k0 + row) * N + n0 + c4 * 4);
        }
        __syncthreads();
#pragma unroll
        for (int kk = 0; kk < 16; kk++) {
            float a[8], b[4];
            *(float4*)(a)     = *(const float4*)&As[kk][ty * 8];
            *(float4*)(a + 4) = *(const float4*)&As[kk][ty * 8 + 4];
            *(float4*)(b)     = *(const float4*)&Bs[kk][tx * 4];
#pragma unroll
            for (int i = 0; i < 8; i++)
#pragma unroll
                for (int j = 0; j < 4; j++)
                    acc[i][j] = fmaf(a[i], b[j], acc[i][j]);
        }
        __syncthreads();
    }
#pragma unroll
    for (int i = 0; i < 8; i++) {
        float4 v = make_float4(acc[i][0], acc[i][1], acc[i][2], acc[i][3]);
        *(float4*)(Cout + (size_t)(m0 + ty * 8 + i) * N + n0 + tx * 4) = v;
    }
}

// ---------------- depthwise 3x3 SAME + q/k/v split ----------------
// One thread per (pixel, 4 channels). Writes q/k/v into contiguous [b,pix,192] buffers.
__global__ __launch_bounds__(256) void dwconv_split_kernel(const float* __restrict__ w)
{
    int gid = blockIdx.x * 256 + threadIdx.x;   // total = NB*HW*144
    int c4 = gid % 144;
    int p  = gid / 144;                         // global pixel index b*HW + pix
    int x  = p % WW;
    int y  = (p / WW) % HH;
    int b  = p / HW;
    int c  = c4 * 4;

    float4 acc = make_float4(0.f, 0.f, 0.f, 0.f);
#pragma unroll
    for (int dy = -1; dy <= 1; dy++) {
        int yy = y + dy;
        if (yy < 0 || yy >= HH) continue;
#pragma unroll
        for (int dx = -1; dx <= 1; dx++) {
            int xx = x + dx;
            if (xx < 0 || xx >= WW) continue;
            const float4 iv = *(const float4*)(g_qkv + ((size_t)((b * HH + yy) * WW + xx)) * C3 + c);
            const float4 wv = *(const float4*)(w + (size_t)((dy + 1) * 3 + (dx + 1)) * C3 + c);
            acc.x = fmaf(iv.x, wv.x, acc.x);
            acc.y = fmaf(iv.y, wv.y, acc.y);
            acc.z = fmaf(iv.z, wv.z, acc.z);
            acc.w = fmaf(iv.w, wv.w, acc.w);
        }
    }
    float* dst; int cc;
    if (c < NC)          { dst = g_q; cc = c; }
    else if (c < 2 * NC) { dst = g_k; cc = c - NC; }
    else                 { dst = g_v; cc = c - 2 * NC; }
    *(float4*)(dst + (size_t)p * NC + cc) = acc;
}

// ---------------- zero attn accumulator ----------------
__global__ void zero_attn_kernel()
{
    int i = blockIdx.x * 256 + threadIdx.x;
    if (i < BNT * CH * CH) g_attn[i] = 0.f;
}

// ---------------- per-row inverse L2 norm ----------------
// grid.x = BNT*CH rows, grid.y = 0 (q) / 1 (k)
__global__ __launch_bounds__(256) void rownorm_kernel()
{
    int r = blockIdx.x;
    const float* src = (blockIdx.y == 0 ? g_q : g_k) + (size_t)r * HW;
    float s = 0.f;
    for (int i = threadIdx.x; i < HW / 4; i += 256) {
        float4 v = ((const float4*)src)[i];
        s += v.x * v.x + v.y * v.y + v.z * v.z + v.w * v.w;
    }
    __shared__ float red[8];
#pragma unroll
    for (int o = 16; o > 0; o >>= 1) s += __shfl_xor_sync(~0u, s, o);
    if ((threadIdx.x & 31) == 0) red[threadIdx.x >> 5] = s;
    __syncthreads();
    if (threadIdx.x < 8) {
        float v = red[threadIdx.x];
#pragma unroll
        for (int o = 4; o > 0; o >>= 1) v += __shfl_xor_sync(0xffu, v, o);
        if (threadIdx.x == 0)
            (blockIdx.y == 0 ? g_invq : g_invk)[r] = rsqrtf(fmaxf(v, 1e-12f));
    }
}

// ---------------- QK^T: 48x48 raw dot per (b,n), split over s ----------------
// grid (32, 8): each block covers 2048 s positions, atomicAdd into g_attn.
__global__ __launch_bounds__(256) void qk_kernel()
{
    int bn    = blockIdx.x;
    int split = blockIdx.y;
    const float* qb = g_q + (size_t)bn * CH * HW;
    const float* kb = g_k + (size_t)bn * CH * HW;

    __shared__ float Qs[CH][65];
    __shared__ float Ks[CH][65];

    int t  = threadIdx.x;
    int d0 = (t >> 4) * 3;   // 0..45
    int e0 = (t & 15) * 3;

    float acc[3][3];
#pragma unroll
    for (int i = 0; i < 3; i++)
#pragma unroll
        for (int j = 0; j < 3; j++) acc[i][j] = 0.f;

    for (int chunk = 0; chunk < 32; chunk++) {
        int s0 = split * 2048 + chunk * 64;
#pragma unroll
        for (int i = 0; i < 3; i++) {
            int fidx = t + 256 * i;          // 0..767
            int r    = fidx >> 4;            // 0..47
            int c4   = fidx & 15;            // 0..15
            float4 qv = *(const float4*)(qb + (size_t)r * HW + s0 + c4 * 4);
            Qs[r][c4 * 4 + 0] = qv.x; Qs[r][c4 * 4 + 1] = qv.y;
            Qs[r][c4 * 4 + 2] = qv.z; Qs[r][c4 * 4 + 3] = qv.w;
            float4 kv = *(const float4*)(kb + (size_t)r * HW + s0 + c4 * 4);
            Ks[r][c4 * 4 + 0] = kv.x; Ks[r][c4 * 4 + 1] = kv.y;
            Ks[r][c4 * 4 + 2] = kv.z; Ks[r][c4 * 4 + 3] = kv.w;
        }
        __syncthreads();
#pragma unroll 8
        for (int ss = 0; ss < 64; ss++) {
            float q0 = Qs[d0][ss], q1 = Qs[d0 + 1][ss], q2 = Qs[d0 + 2][ss];
            float k0 = Ks[e0][ss], k1 = Ks[e0 + 1][ss], k2 = Ks[e0 + 2][ss];
            acc[0][0] = fmaf(q0, k0, acc[0][0]);
            acc[0][1] = fmaf(q0, k1, acc[0][1]);
            acc[0][2] = fmaf(q0, k2, acc[0][2]);
            acc[1][0] = fmaf(q1, k0, acc[1][0]);
            acc[1][1] = fmaf(q1, k1, acc[1][1]);
            acc[1][2] = fmaf(q1, k2, acc[1][2]);
            acc[2][0] = fmaf(q2, k0, acc[2][0]);
            acc[2][1] = fmaf(q2, k1, acc[2][1]);
            acc[2][2] = fmaf(q2, k2, acc[2][2]);
        }
        __syncthreads();
    }
#pragma unroll
    for (int i = 0; i < 3; i++)
#pragma unroll
        for (int j = 0; j < 3; j++)
            atomicAdd(&g_attn[bn * CH * CH + (d0 + i) * CH + (e0 + j)], acc[i][j]);
}

// ---------------- softmax with l2-norm scaling + temperature ----------------
// grid = BNT*CH rows, 32 threads/row. In-place on g_attn.
__global__ void softmax48_kernel(const float* __restrict__ temp)
{
    int row = blockIdx.x;              // bn*48 + dq
    int bn  = row / CH;
    int n   = bn & (HEADS - 1);
    int l   = threadIdx.x;             // 0..31
    float tf = temp[n];
    float iq = g_invq[row];
    float* arow = g_attn + (size_t)row * CH;

    float v0 = arow[l] * iq * g_invk[bn * CH + l] * tf;
    float v1 = (l < 16) ? arow[l + 32] * iq * g_invk[bn * CH + l + 32] * tf : -3.0e38f;
    float m = fmaxf(v0, v1);
#pragma unroll
    for (int o = 16; o > 0; o >>= 1) m = fmaxf(m, __shfl_xor_sync(~0u, m, o));
    float e0 = expf(v0 - m);
    float e1 = (l < 16) ? expf(v1 - m) : 0.f;
    float s = e0 + e1;
#pragma unroll
    for (int o = 16; o > 0; o >>= 1) s += __shfl_xor_sync(~0u, s, o);
    float inv = 1.f / s;
    arow[l] = e0 * inv;
    if (l < 16) arow[l + 32] = e1 * inv;
}

// ---------------- out = attn @ V, written contiguous [bn*48+d, s] ----------------
// grid (32, 32): each thread handles one float2 of s (2 positions). attn in smem.
__global__ __launch_bounds__(256) void av_kernel()
{
    int bn = blockIdx.x;
    int s2 = blockIdx.y * 256 + threadIdx.x;     // 0..8191 (float2 index)

    __shared__ float As[CH * CH];
    for (int f = threadIdx.x; f < CH * CH; f += 256) As[f] = g_attn[bn * CH * CH + f];
    __syncthreads();

    const float2* vb = (const float2*)(g_v + (size_t)bn * CH * HW) + s2;
    float2 vr[CH];
#pragma unroll
    for (int e = 0; e < CH; e++) vr[e] = vb[(size_t)e * (HW / 2)];

    float2* ob = (float2*)(g_o + (size_t)bn * CH * HW) + s2;
    for (int d = 0; d < CH; d++) {
        float2 a = make_float2(0.f, 0.f);
#pragma unroll
        for (int e = 0; e < CH; e++) {
            float w = As[d * CH + e];
            a.x = fmaf(w, vr[e].x, a.x);
            a.y = fmaf(w, vr[e].y, a.y);
        }
        ob[(size_t)d * (HW / 2)] = a;
    }
}

// ---------------- launch ----------------
extern "C" void kernel_launch(void* const* d_in, const int* in_sizes, int n_in,
                              void* d_out, int out_size)
{
    const float* x      = (const float*)d_in[0];  // [8,128,128,192]
    const float* qkv_w  = (const float*)d_in[1];  // [192,576]
    const float* dw_w   = (const float*)d_in[2];  // [3,3,1,576]
    const float* proj_w = (const float*)d_in[3];  // [192,192]
    const float* temp   = (const float*)d_in[4];  // [4,1,1]
    float* out = (float*)d_out;

    float *qkv_buf, *o_buf;
    cudaGetSymbolAddress((void**)&qkv_buf, g_qkv);
    cudaGetSymbolAddress((void**)&o_buf, g_o);

    const int M = NB * HW;   // 131072

    // 1) qkv = x @ qkv_w    [131072,192] x [192,576]
    sgemm_k192<<<dim3(M / 128, C3 / 64), 256>>>(x, qkv_w, qkv_buf, C3);

    // 2) depthwise 3x3 + split into contiguous q/k/v
    dwconv_split_kernel<<<(NB * HW * (C3 / 4)) / 256, 256>>>(dw_w);

    // 3) zero attn accumulator
    zero_attn_kernel<<<(BNT * CH * CH + 255) / 256, 256>>>();

    // 4) row inverse L2 norms for q and k
    rownorm_kernel<<<dim3(BNT * CH, 2), 256>>>();

    // 5) raw QK^T with split-s atomics
    qk_kernel<<<dim3(BNT, 8), 256>>>();

    // 6) scale + softmax
    softmax48_kernel<<<BNT * CH, 32>>>(temp);

    // 7) out = attn @ V (contiguous layout doubles as [b*hw,192])
    av_kernel<<<dim3(BNT, HW / 512), 256>>>();

    // 8) projection GEMM -> d_out
    sgemm_k192<<<dim3(M / 128, NC / 64), 256>>>(o_buf, proj_w, out, NC);
}

// round 3
// speedup vs baseline: 1.4807x; 1.4807x over previous
#include <cuda_runtime.h>
#include <cuda_bf16.h>
#include <math.h>
#include <stdint.h>

#define NB 8
#define HH 128
#define WW 128
#define NC 192
#define C3 576
#define HEADS 4
#define CH 48
#define HW 16384
#define BNT 32
#define KDIM 192

// ---------------- scratch ----------------
__device__ float g_qkv[(size_t)NB * HW * C3];
__device__ float g_q[(size_t)NB * HW * NC];
__device__ float g_k[(size_t)NB * HW * NC];
__device__ float g_v[(size_t)NB * HW * NC];
__device__ float g_o[(size_t)NB * HW * NC];
__device__ float g_attn[BNT * CH * CH];
__device__ float g_ssq_q[BNT * CH];
__device__ float g_ssq_k[BNT * CH];
// weights pre-transposed + bf16-split: [N][K] layout
__device__ __nv_bfloat16 g_wqkv_h[C3 * KDIM];
__device__ __nv_bfloat16 g_wqkv_l[C3 * KDIM];
__device__ __nv_bfloat16 g_wproj_h[NC * KDIM];
__device__ __nv_bfloat16 g_wproj_l[NC * KDIM];

// ---------------- helpers ----------------
__device__ __forceinline__ uint32_t pk_hi(float a, float b) {
    __nv_bfloat16 ha = __float2bfloat16(a), hb = __float2bfloat16(b);
    uint16_t ra = *(uint16_t*)&ha, rb = *(uint16_t*)&hb;
    return (uint32_t)ra | ((uint32_t)rb << 16);
}
__device__ __forceinline__ uint32_t pk_lo(float a, float b) {
    __nv_bfloat16 ha = __float2bfloat16(a), hb = __float2bfloat16(b);
    float la = a - __bfloat162float(ha), lb = b - __bfloat162float(hb);
    __nv_bfloat16 xa = __float2bfloat16(la), xb = __float2bfloat16(lb);
    uint16_t ra = *(uint16_t*)&xa, rb = *(uint16_t*)&xb;
    return (uint32_t)ra | ((uint32_t)rb << 16);
}

__device__ __forceinline__ void mma16816(float* c, const uint32_t* a, const uint32_t* b) {
    asm volatile(
        "mma.sync.aligned.m16n8k16.row.col.f32.bf16.bf16.f32 "
        "{%0,%1,%2,%3}, {%4,%5,%6,%7}, {%8,%9}, {%0,%1,%2,%3};\n"
        : "+f"(c[0]), "+f"(c[1]), "+f"(c[2]), "+f"(c[3])
        : "r"(a[0]), "r"(a[1]), "r"(a[2]), "r"(a[3]), "r"(b[0]), "r"(b[1]));
}

// ---------------- weight prep: transpose + bf16 split ----------------
__global__ void wprep_kernel(const float* __restrict__ qkvw, const float* __restrict__ projw)
{
    int i = blockIdx.x * 256 + threadIdx.x;
    if (i < C3 * KDIM) {
        int n = i / KDIM, k = i % KDIM;
        float v = qkvw[(size_t)k * C3 + n];
        __nv_bfloat16 h = __float2bfloat16(v);
        g_wqkv_h[i] = h;
        g_wqkv_l[i] = __float2bfloat16(v - __bfloat162float(h));
    }
    if (i < NC * KDIM) {
        int n = i / KDIM, k = i % KDIM;
        float v = projw[(size_t)k * NC + n];
        __nv_bfloat16 h = __float2bfloat16(v);
        g_wproj_h[i] = h;
        g_wproj_l[i] = __float2bfloat16(v - __bfloat162float(h));
    }
}

// ---------------- mma.sync bf16-split GEMM ----------------
// [M,192]fp32 x W[N,192]bf16(hi/lo) -> [M,N]fp32.
// CTA: 128 M-rows, loops all N in chunks of 64. 256 threads = 8 warps (4 M x 2 N),
// warp tile 32x32, m16n8k16 fragments via padded conflict-free lds.
#define ASTRIDE 200   // padded bf16 row stride
#define OFF_AH 0
#define OFF_AL (128 * ASTRIDE * 2)
#define OFF_BH (OFF_AL + 128 * ASTRIDE * 2)
#define OFF_BL (OFF_BH + 64 * ASTRIDE * 2)
#define GEMM_SMEM (OFF_BL + 64 * ASTRIDE * 2)   // 153600 bytes

__global__ __launch_bounds__(256) void gemm_mma_split(
    const float* __restrict__ A, const __nv_bfloat16* __restrict__ Wh,
    const __nv_bfloat16* __restrict__ Wl, float* __restrict__ Cout, int Ntot)
{
    extern __shared__ char smem[];
    __nv_bfloat16 (*Ah)[ASTRIDE] = (__nv_bfloat16(*)[ASTRIDE])(smem + OFF_AH);
    __nv_bfloat16 (*Al)[ASTRIDE] = (__nv_bfloat16(*)[ASTRIDE])(smem + OFF_AL);
    __nv_bfloat16 (*Bh)[ASTRIDE] = (__nv_bfloat16(*)[ASTRIDE])(smem + OFF_BH);
    __nv_bfloat16 (*Bl)[ASTRIDE] = (__nv_bfloat16(*)[ASTRIDE])(smem + OFF_BL);

    const int t = threadIdx.x;
    const int warp = t >> 5, lane = t & 31;
    const int grp = lane >> 2, tig = lane & 3;
    const int warpM = warp >> 1, warpN = warp & 1;     // 4 x 2
    const size_t m0 = (size_t)blockIdx.x * 128;

    // ---- A tile: fp32 -> bf16 hi/lo in smem (once) ----
    {
        int row = t >> 1, half = t & 1;
        const float4* ar = (const float4*)(A + (m0 + row) * KDIM + half * 96);
#pragma unroll
        for (int j = 0; j < 24; j++) {
            float4 v = ar[j];
            int col = half * 96 + j * 4;
            *(uint32_t*)&Ah[row][col]     = pk_hi(v.x, v.y);
            *(uint32_t*)&Ah[row][col + 2] = pk_hi(v.z, v.w);
            *(uint32_t*)&Al[row][col]     = pk_lo(v.x, v.y);
            *(uint32_t*)&Al[row][col + 2] = pk_lo(v.z, v.w);
        }
    }

    const int nChunks = Ntot >> 6;
    float c[2][4][4];

    for (int nc = 0; nc < nChunks; nc++) {
        int n0 = nc * 64;
        __syncthreads();   // prior mma done reading B (and A ready on first iter)
        // ---- B chunk: 64 rows x 192 bf16, hi and lo ----
        {
            const uint4* bh = (const uint4*)(Wh + (size_t)n0 * KDIM);
            const uint4* bl = (const uint4*)(Wl + (size_t)n0 * KDIM);
#pragma unroll
            for (int i = t; i < 1536; i += 256) {   // 64 rows * 24 uint4
                int row = i / 24, c8 = (i % 24) * 8;
                *(uint4*)&Bh[row][c8] = bh[i];
                *(uint4*)&Bl[row][c8] = bl[i];
            }
        }
        __syncthreads();

#pragma unroll
        for (int mi = 0; mi < 2; mi++)
#pragma unroll
            for (int ni = 0; ni < 4; ni++)
#pragma unroll
                for (int j = 0; j < 4; j++) c[mi][ni][j] = 0.f;

#pragma unroll 1
        for (int pass = 0; pass < 3; pass++) {
            __nv_bfloat16 (*As)[ASTRIDE] = (pass == 2) ? Al : Ah;
            __nv_bfloat16 (*Bs)[ASTRIDE] = (pass == 1) ? Bl : Bh;
#pragma unroll
            for (int ks = 0; ks < 12; ks++) {
                int k0 = ks * 16;
                uint32_t ua[2][4], ub[4][2];
#pragma unroll
                for (int mi = 0; mi < 2; mi++) {
                    int mrow = warpM * 32 + mi * 16 + grp;
                    ua[mi][0] = *(const uint32_t*)&As[mrow][k0 + tig * 2];
                    ua[mi][1] = *(const uint32_t*)&As[mrow + 8][k0 + tig * 2];
                    ua[mi][2] = *(const uint32_t*)&As[mrow][k0 + tig * 2 + 8];
                    ua[mi][3] = *(const uint32_t*)&As[mrow + 8][k0 + tig * 2 + 8];
                }
#pragma unroll
                for (int ni = 0; ni < 4; ni++) {
                    int ncol = warpN * 32 + ni * 8 + grp;
                    ub[ni][0] = *(const uint32_t*)&Bs[ncol][k0 + tig * 2];
                    ub[ni][1] = *(const uint32_t*)&Bs[ncol][k0 + tig * 2 + 8];
                }
#pragma unroll
                for (int mi = 0; mi < 2; mi++)
#pragma unroll
                    for (int ni = 0; ni < 4; ni++)
                        mma16816(c[mi][ni], ua[mi], ub[ni]);
            }
        }

        // ---- epilogue: store 128x64 chunk ----
#pragma unroll
        for (int mi = 0; mi < 2; mi++) {
            size_t row = m0 + warpM * 32 + mi * 16 + grp;
#pragma unroll
            for (int ni = 0; ni < 4; ni++) {
                int col = n0 + warpN * 32 + ni * 8 + tig * 2;
                *(float2*)(Cout + row * Ntot + col) = make_float2(c[mi][ni][0], c[mi][ni][1]);
                *(float2*)(Cout + (row + 8) * Ntot + col) = make_float2(c[mi][ni][2], c[mi][ni][3]);
            }
        }
    }
}

// ---------------- depthwise 3x3 SAME + q/k/v split ----------------
__global__ __launch_bounds__(256) void dwconv_split_kernel(const float* __restrict__ w)
{
    int gid = blockIdx.x * 256 + threadIdx.x;
    int c4 = gid % 144;
    int p = gid / 144;
    int x = p % WW;
    int y = (p / WW) % HH;
    int b = p / HW;
    int c = c4 * 4;

    float4 acc = make_float4(0.f, 0.f, 0.f, 0.f);
#pragma unroll
    for (int dy = -1; dy <= 1; dy++) {
        int yy = y + dy;
        if (yy < 0 || yy >= HH) continue;
#pragma unroll
        for (int dx = -1; dx <= 1; dx++) {
            int xx = x + dx;
            if (xx < 0 || xx >= WW) continue;
            const float4 iv = *(const float4*)(g_qkv + ((size_t)((b * HH + yy) * WW + xx)) * C3 + c);
            const float4 wv = *(const float4*)(w + (size_t)((dy + 1) * 3 + (dx + 1)) * C3 + c);
            acc.x = fmaf(iv.x, wv.x, acc.x);
            acc.y = fmaf(iv.y, wv.y, acc.y);
            acc.z = fmaf(iv.z, wv.z, acc.z);
            acc.w = fmaf(iv.w, wv.w, acc.w);
        }
    }
    float* dst; int cc;
    if (c < NC)          { dst = g_q; cc = c; }
    else if (c < 2 * NC) { dst = g_k; cc = c - NC; }
    else                 { dst = g_v; cc = c - 2 * NC; }
    *(float4*)(dst + (size_t)p * NC + cc) = acc;
}

// ---------------- zero attn + ssq ----------------
__global__ void zero_kernel()
{
    int i = blockIdx.x * 256 + threadIdx.x;
    if (i < BNT * CH * CH) g_attn[i] = 0.f;
    if (i < BNT * CH) { g_ssq_q[i] = 0.f; g_ssq_k[i] = 0.f; }
}

// ---------------- QK^T + fused square-sums ----------------
__global__ __launch_bounds__(256) void qk_kernel()
{
    int bn = blockIdx.x;
    int split = blockIdx.y;
    const float* qb = g_q + (size_t)bn * CH * HW;
    const float* kb = g_k + (size_t)bn * CH * HW;

    __shared__ float Qs[CH][65];
    __shared__ float Ks[CH][65];

    int t = threadIdx.x;
    int d0 = (t >> 4) * 3;
    int e0 = (t & 15) * 3;

    float acc[3][3];
#pragma unroll
    for (int i = 0; i < 3; i++)
#pragma unroll
        for (int j = 0; j < 3; j++) acc[i][j] = 0.f;
    float qss[3] = {0.f, 0.f, 0.f}, kss[3] = {0.f, 0.f, 0.f};

    for (int chunk = 0; chunk < 32; chunk++) {
        int s0 = split * 2048 + chunk * 64;
#pragma unroll
        for (int i = 0; i < 3; i++) {
            int fidx = t + 256 * i;
            int r = fidx >> 4;
            int c4 = fidx & 15;
            float4 qv = *(const float4*)(qb + (size_t)r * HW + s0 + c4 * 4);
            Qs[r][c4 * 4 + 0] = qv.x; Qs[r][c4 * 4 + 1] = qv.y;
            Qs[r][c4 * 4 + 2] = qv.z; Qs[r][c4 * 4 + 3] = qv.w;
            qss[i] += qv.x * qv.x + qv.y * qv.y + qv.z * qv.z + qv.w * qv.w;
            float4 kv = *(const float4*)(kb + (size_t)r * HW + s0 + c4 * 4);
            Ks[r][c4 * 4 + 0] = kv.x; Ks[r][c4 * 4 + 1] = kv.y;
            Ks[r][c4 * 4 + 2] = kv.z; Ks[r][c4 * 4 + 3] = kv.w;
            kss[i] += kv.x * kv.x + kv.y * kv.y + kv.z * kv.z + kv.w * kv.w;
        }
        __syncthreads();
#pragma unroll 8
        for (int ss = 0; ss < 64; ss++) {
            float q0 = Qs[d0][ss], q1 = Qs[d0 + 1][ss], q2 = Qs[d0 + 2][ss];
            float k0 = Ks[e0][ss], k1 = Ks[e0 + 1][ss], k2 = Ks[e0 + 2][ss];
            acc[0][0] = fmaf(q0, k0, acc[0][0]);
            acc[0][1] = fmaf(q0, k1, acc[0][1]);
            acc[0][2] = fmaf(q0, k2, acc[0][2]);
            acc[1][0] = fmaf(q1, k0, acc[1][0]);
            acc[1][1] = fmaf(q1, k1, acc[1][1]);
            acc[1][2] = fmaf(q1, k2, acc[1][2]);
            acc[2][0] = fmaf(q2, k0, acc[2][0]);
            acc[2][1] = fmaf(q2, k1, acc[2][1]);
            acc[2][2] = fmaf(q2, k2, acc[2][2]);
        }
        __syncthreads();
    }
#pragma unroll
    for (int i = 0; i < 3; i++)
#pragma unroll
        for (int o = 8; o > 0; o >>= 1) {
            qss[i] += __shfl_xor_sync(~0u, qss[i], o);
            kss[i] += __shfl_xor_sync(~0u, kss[i], o);
        }
    if ((t & 15) == 0) {
        int rbase = bn * CH + (t >> 4);
#pragma unroll
        for (int i = 0; i < 3; i++) {
            atomicAdd(&g_ssq_q[rbase + 16 * i], qss[i]);
            atomicAdd(&g_ssq_k[rbase + 16 * i], kss[i]);
        }
    }
#pragma unroll
    for (int i = 0; i < 3; i++)
#pragma unroll
        for (int j = 0; j < 3; j++)
            atomicAdd(&g_attn[bn * CH * CH + (d0 + i) * CH + (e0 + j)], acc[i][j]);
}

// ---------------- softmax with l2-norm scaling + temperature ----------------
__global__ void softmax48_kernel(const float* __restrict__ temp)
{
    int row = blockIdx.x;
    int bn = row / CH;
    int n = bn & (HEADS - 1);
    int l = threadIdx.x;
    float tf = temp[n];
    float iq = rsqrtf(fmaxf(g_ssq_q[row], 1e-12f));
    float* arow = g_attn + (size_t)row * CH;

    float ik0 = rsqrtf(fmaxf(g_ssq_k[bn * CH + l], 1e-12f));
    float v0 = arow[l] * iq * ik0 * tf;
    float v1 = -3.0e38f;
    if (l < 16) {
        float ik1 = rsqrtf(fmaxf(g_ssq_k[bn * CH + l + 32], 1e-12f));
        v1 = arow[l + 32] * iq * ik1 * tf;
    }
    float m = fmaxf(v0, v1);
#pragma unroll
    for (int o = 16; o > 0; o >>= 1) m = fmaxf(m, __shfl_xor_sync(~0u, m, o));
    float e0 = expf(v0 - m);
    float e1 = (l < 16) ? expf(v1 - m) : 0.f;
    float s = e0 + e1;
#pragma unroll
    for (int o = 16; o > 0; o >>= 1) s += __shfl_xor_sync(~0u, s, o);
    float inv = 1.f / s;
    arow[l] = e0 * inv;
    if (l < 16) arow[l + 32] = e1 * inv;
}

// ---------------- out = attn @ V ----------------
__global__ __launch_bounds__(256) void av_kernel()
{
    int bn = blockIdx.x;
    int s2 = blockIdx.y * 256 + threadIdx.x;

    __shared__ float As[CH * CH];
    for (int f = threadIdx.x; f < CH * CH; f += 256) As[f] = g_attn[bn * CH * CH + f];
    __syncthreads();

    const float2* vb = (const float2*)(g_v + (size_t)bn * CH * HW) + s2;
    float2 vr[CH];
#pragma unroll
    for (int e = 0; e < CH; e++) vr[e] = vb[(size_t)e * (HW / 2)];

    float2* ob = (float2*)(g_o + (size_t)bn * CH * HW) + s2;
    for (int d = 0; d < CH; d++) {
        float2 a = make_float2(0.f, 0.f);
#pragma unroll
        for (int e = 0; e < CH; e++) {
            float w = As[d * CH + e];
            a.x = fmaf(w, vr[e].x, a.x);
            a.y = fmaf(w, vr[e].y, a.y);
        }
        ob[(size_t)d * (HW / 2)] = a;
    }
}

// ---------------- launch ----------------
extern "C" void kernel_launch(void* const* d_in, const int* in_sizes, int n_in,
                              void* d_out, int out_size)
{
    const float* x      = (const float*)d_in[0];
    const float* qkv_w  = (const float*)d_in[1];
    const float* dw_w   = (const float*)d_in[2];
    const float* proj_w = (const float*)d_in[3];
    const float* temp   = (const float*)d_in[4];
    float* out = (float*)d_out;

    float *qkv_buf, *o_buf;
    cudaGetSymbolAddress((void**)&qkv_buf, g_qkv);
    cudaGetSymbolAddress((void**)&o_buf, g_o);
    __nv_bfloat16 *wqh, *wql, *wph, *wpl;
    cudaGetSymbolAddress((void**)&wqh, g_wqkv_h);
    cudaGetSymbolAddress((void**)&wql, g_wqkv_l);
    cudaGetSymbolAddress((void**)&wph, g_wproj_h);
    cudaGetSymbolAddress((void**)&wpl, g_wproj_l);

    cudaFuncSetAttribute(gemm_mma_split, cudaFuncAttributeMaxDynamicSharedMemorySize, GEMM_SMEM);

    const int M = NB * HW;

    // 0) weight transpose + bf16 split
    wprep_kernel<<<(C3 * KDIM + 255) / 256, 256>>>(qkv_w, proj_w);

    // 1) qkv = x @ qkv_w  (mma.sync bf16-split)
    gemm_mma_split<<<M / 128, 256, GEMM_SMEM>>>(x, wqh, wql, qkv_buf, C3);

    // 2) depthwise 3x3 + split
    dwconv_split_kernel<<<(NB * HW * (C3 / 4)) / 256, 256>>>(dw_w);

    // 3) zero attn + ssq
    zero_kernel<<<(BNT * CH * CH + 255) / 256, 256>>>();

    // 4) QK^T + fused square sums
    qk_kernel<<<dim3(BNT, 8), 256>>>();

    // 5) scale + softmax
    softmax48_kernel<<<BNT * CH, 32>>>(temp);

    // 6) out = attn @ V
    av_kernel<<<dim3(BNT, HW / 512), 256>>>();

    // 7) projection (mma.sync bf16-split)
    gemm_mma_split<<<M / 128, 256, GEMM_SMEM>>>(o_buf, wph, wpl, out, NC);
}

// round 4
// speedup vs baseline: 1.5286x; 1.0324x over previous
#include <cuda_runtime.h>
#include <cuda_bf16.h>
#include <math.h>
#include <stdint.h>

#define NB 8
#define HH 128
#define WW 128
#define NC 192
#define C3 576
#define HEADS 4
#define CH 48
#define HW 16384
#define BNT 32
#define KDIM 192

// ---------------- scratch ----------------
__device__ float g_qkv[(size_t)NB * HW * C3];
__device__ float g_q[(size_t)NB * HW * NC];
__device__ float g_k[(size_t)NB * HW * NC];
__device__ float g_v[(size_t)NB * HW * NC];
__device__ float g_o[(size_t)NB * HW * NC];
__device__ float g_attn[BNT * CH * CH];
__device__ float g_ssq_q[BNT * CH];
__device__ float g_ssq_k[BNT * CH];
__device__ __nv_bfloat16 g_wqkv_h[C3 * KDIM];
__device__ __nv_bfloat16 g_wqkv_l[C3 * KDIM];
__device__ __nv_bfloat16 g_wproj_h[NC * KDIM];
__device__ __nv_bfloat16 g_wproj_l[NC * KDIM];

// ---------------- helpers ----------------
__device__ __forceinline__ uint32_t smem_u32(const void* p) {
    uint32_t a;
    asm("{ .reg .u64 t; cvta.to.shared.u64 t, %1; cvt.u32.u64 %0, t; }" : "=r"(a) : "l"(p));
    return a;
}
__device__ __forceinline__ uint32_t pk_hi(float a, float b) {
    __nv_bfloat16 ha = __float2bfloat16(a), hb = __float2bfloat16(b);
    uint16_t ra = *(uint16_t*)&ha, rb = *(uint16_t*)&hb;
    return (uint32_t)ra | ((uint32_t)rb << 16);
}
__device__ __forceinline__ uint32_t pk_lo(float a, float b) {
    __nv_bfloat16 ha = __float2bfloat16(a), hb = __float2bfloat16(b);
    float la = a - __bfloat162float(ha), lb = b - __bfloat162float(hb);
    __nv_bfloat16 xa = __float2bfloat16(la), xb = __float2bfloat16(lb);
    uint16_t ra = *(uint16_t*)&xa, rb = *(uint16_t*)&xb;
    return (uint32_t)ra | ((uint32_t)rb << 16);
}
__device__ __forceinline__ void mma16816(float* c, const uint32_t* a, const uint32_t* b) {
    asm volatile(
        "mma.sync.aligned.m16n8k16.row.col.f32.bf16.bf16.f32 "
        "{%0,%1,%2,%3}, {%4,%5,%6,%7}, {%8,%9}, {%0,%1,%2,%3};\n"
        : "+f"(c[0]), "+f"(c[1]), "+f"(c[2]), "+f"(c[3])
        : "r"(a[0]), "r"(a[1]), "r"(a[2]), "r"(a[3]), "r"(b[0]), "r"(b[1]));
}
__device__ __forceinline__ void ldmx4(uint32_t* r, uint32_t addr) {
    asm volatile("ldmatrix.sync.aligned.m8n8.x4.shared.b16 {%0,%1,%2,%3}, [%4];"
        : "=r"(r[0]), "=r"(r[1]), "=r"(r[2]), "=r"(r[3]) : "r"(addr));
}
#define CP_ASYNC16(dst, src) asm volatile("cp.async.ca.shared.global [%0], [%1], 16;" :: "r"(dst), "l"(src))
#define CP_COMMIT()          asm volatile("cp.async.commit_group;" ::: "memory")
#define CP_WAIT(n)           asm volatile("cp.async.wait_group %0;" :: "n"(n) : "memory")

// ---------------- weight prep + zero scratch ----------------
__global__ void wprep_kernel(const float* __restrict__ qkvw, const float* __restrict__ projw)
{
    int i = blockIdx.x * 256 + threadIdx.x;
    if (i < C3 * KDIM) {
        int n = i / KDIM, k = i % KDIM;
        float v = qkvw[(size_t)k * C3 + n];
        __nv_bfloat16 h = __float2bfloat16(v);
        g_wqkv_h[i] = h;
        g_wqkv_l[i] = __float2bfloat16(v - __bfloat162float(h));
    }
    if (i < NC * KDIM) {
        int n = i / KDIM, k = i % KDIM;
        float v = projw[(size_t)k * NC + n];
        __nv_bfloat16 h = __float2bfloat16(v);
        g_wproj_h[i] = h;
        g_wproj_l[i] = __float2bfloat16(v - __bfloat162float(h));
    }
    if (i < BNT * CH * CH) g_attn[i] = 0.f;
    if (i < BNT * CH) { g_ssq_q[i] = 0.f; g_ssq_k[i] = 0.f; }
}

// ---------------- mma.sync bf16-split GEMM (ldmatrix + fused passes + cp.async) ----------------
// [M,192]fp32 x W[N,192]bf16(hi/lo) -> [M,N]fp32.
// CTA = 128 M-rows; loops N in 64-chunks. 8 warps (4M x 2N), warp tile 32x32.
// D = Ah*Bh + Ah*Bl + Al*Bh accumulated in one k-loop.
#define ASTRIDE 200                    // bf16 elements per padded row (400 bytes)
#define ROWB    (ASTRIDE * 2)          // 400
#define OFF_AH  0
#define OFF_AL  (128 * ROWB)           // 51200
#define OFF_B   (2 * 128 * ROWB)       // 102400
#define BBUF    (64 * ROWB * 2)        // one buffer: Bh + Bl = 51200
#define GEMM_SMEM (OFF_B + 2 * BBUF)   // 204800

__global__ __launch_bounds__(256) void gemm_mma_split(
    const float* __restrict__ A, const __nv_bfloat16* __restrict__ Wh,
    const __nv_bfloat16* __restrict__ Wl, float* __restrict__ Cout, int Ntot)
{
    extern __shared__ char smem[];
    const uint32_t sbase = smem_u32(smem);
    const uint32_t sAh = sbase + OFF_AH;
    const uint32_t sAl = sbase + OFF_AL;

    const int t = threadIdx.x;
    const int warp = t >> 5, lane = t & 31;
    const int grp = lane >> 2, tig = lane & 3;
    const int warpM = warp >> 1, warpN = warp & 1;
    const size_t m0 = (size_t)blockIdx.x * 128;
    const int nChunks = Ntot >> 6;

    // ldmatrix per-lane byte offsets (within A / B regions)
    const uint32_t aOff = (uint32_t)(warpM * 32 + (lane & 15)) * ROWB + ((lane >> 4) * 16);
    const uint32_t bOff = (uint32_t)(warpN * 32 + ((lane >> 4) * 8) + (lane & 7)) * ROWB
                          + (((lane >> 3) & 1) * 16);

    // ---- prologue: async-load B chunk 0, then convert A ----
    {
        const uint4* bh = (const uint4*)Wh;        // chunk 0 at n0=0
        const uint4* bl = (const uint4*)Wl;
        uint32_t dsth = sbase + OFF_B;
        uint32_t dstl = dsth + 64 * ROWB;
#pragma unroll
        for (int i = t; i < 1536; i += 256) {      // 64 rows * 24 uint4
            int row = i / 24, cb = (i % 24) * 16;
            uint32_t o = (uint32_t)row * ROWB + cb;
            CP_ASYNC16(dsth + o, bh + i);
            CP_ASYNC16(dstl + o, bl + i);
        }
        CP_COMMIT();
    }
    {
        int row = t >> 1, half = t & 1;
        const float4* ar = (const float4*)(A + (m0 + row) * KDIM + half * 96);
        __nv_bfloat16* ahp = (__nv_bfloat16*)(smem + OFF_AH) + row * ASTRIDE;
        __nv_bfloat16* alp = (__nv_bfloat16*)(smem + OFF_AL) + row * ASTRIDE;
#pragma unroll
        for (int j = 0; j < 24; j++) {
            float4 v = ar[j];
            int col = half * 96 + j * 4;
            *(uint32_t*)(ahp + col)     = pk_hi(v.x, v.y);
            *(uint32_t*)(ahp + col + 2) = pk_hi(v.z, v.w);
            *(uint32_t*)(alp + col)     = pk_lo(v.x, v.y);
            *(uint32_t*)(alp + col + 2) = pk_lo(v.z, v.w);
        }
    }

    float c[2][4][4];

    for (int nc = 0; nc < nChunks; nc++) {
        // prefetch next B chunk into the other buffer
        if (nc + 1 < nChunks) {
            const uint4* bh = (const uint4*)(Wh + (size_t)(nc + 1) * 64 * KDIM);
            const uint4* bl = (const uint4*)(Wl + (size_t)(nc + 1) * 64 * KDIM);
            uint32_t dsth = sbase + OFF_B + ((nc + 1) & 1) * BBUF;
            uint32_t dstl = dsth + 64 * ROWB;
#pragma unroll
            for (int i = t; i < 1536; i += 256) {
                int row = i / 24, cb = (i % 24) * 16;
                uint32_t o = (uint32_t)row * ROWB + cb;
                CP_ASYNC16(dsth + o, bh + i);
                CP_ASYNC16(dstl + o, bl + i);
            }
            CP_COMMIT();
            CP_WAIT(1);          // chunk nc arrived
        } else {
            CP_WAIT(0);
        }
        __syncthreads();

        const uint32_t sBh = sbase + OFF_B + (nc & 1) * BBUF;
        const uint32_t sBl = sBh + 64 * ROWB;

#pragma unroll
        for (int mi = 0; mi < 2; mi++)
#pragma unroll
            for (int ni = 0; ni < 4; ni++)
#pragma unroll
                for (int j = 0; j < 4; j++) c[mi][ni][j] = 0.f;

#pragma unroll
        for (int ks = 0; ks < 12; ks++) {
            const uint32_t k32 = ks * 32;
            uint32_t ah[2][4], al[2][4], bh[2][4], bl[2][4];
            ldmx4(ah[0], sAh + aOff + k32);
            ldmx4(ah[1], sAh + aOff + 16 * ROWB + k32);
            ldmx4(al[0], sAl + aOff + k32);
            ldmx4(al[1], sAl + aOff + 16 * ROWB + k32);
            ldmx4(bh[0], sBh + bOff + k32);
            ldmx4(bh[1], sBh + bOff + 16 * ROWB + k32);
            ldmx4(bl[0], sBl + bOff + k32);
            ldmx4(bl[1], sBl + bOff + 16 * ROWB + k32);
#pragma unroll
            for (int mi = 0; mi < 2; mi++)
#pragma unroll
                for (int p = 0; p < 2; p++) {
                    mma16816(c[mi][2 * p],     ah[mi], &bh[p][0]);
                    mma16816(c[mi][2 * p + 1], ah[mi], &bh[p][2]);
                    mma16816(c[mi][2 * p],     ah[mi], &bl[p][0]);
                    mma16816(c[mi][2 * p + 1], ah[mi], &bl[p][2]);
                    mma16816(c[mi][2 * p],     al[mi], &bh[p][0]);
                    mma16816(c[mi][2 * p + 1], al[mi], &bh[p][2]);
                }
        }

        // epilogue: store 128x64 chunk
        const int n0 = nc * 64;
#pragma unroll
        for (int mi = 0; mi < 2; mi++) {
            size_t row = m0 + warpM * 32 + mi * 16 + grp;
#pragma unroll
            for (int ni = 0; ni < 4; ni++) {
                int col = n0 + warpN * 32 + ni * 8 + tig * 2;
                *(float2*)(Cout + row * Ntot + col) = make_float2(c[mi][ni][0], c[mi][ni][1]);
                *(float2*)(Cout + (row + 8) * Ntot + col) = make_float2(c[mi][ni][2], c[mi][ni][3]);
            }
        }
        __syncthreads();   // all reads of buf[nc&1] done before it is refilled at nc+2
    }
}

// ---------------- depthwise 3x3 SAME + q/k/v split ----------------
__global__ __launch_bounds__(256) void dwconv_split_kernel(const float* __restrict__ w)
{
    int gid = blockIdx.x * 256 + threadIdx.x;
    int c4 = gid % 144;
    int p = gid / 144;
    int x = p % WW;
    int y = (p / WW) % HH;
    int b = p / HW;
    int c = c4 * 4;

    float4 acc = make_float4(0.f, 0.f, 0.f, 0.f);
#pragma unroll
    for (int dy = -1; dy <= 1; dy++) {
        int yy = y + dy;
        if (yy < 0 || yy >= HH) continue;
#pragma unroll
        for (int dx = -1; dx <= 1; dx++) {
            int xx = x + dx;
            if (xx < 0 || xx >= WW) continue;
            const float4 iv = *(const float4*)(g_qkv + ((size_t)((b * HH + yy) * WW + xx)) * C3 + c);
            const float4 wv = *(const float4*)(w + (size_t)((dy + 1) * 3 + (dx + 1)) * C3 + c);
            acc.x = fmaf(iv.x, wv.x, acc.x);
            acc.y = fmaf(iv.y, wv.y, acc.y);
            acc.z = fmaf(iv.z, wv.z, acc.z);
            acc.w = fmaf(iv.w, wv.w, acc.w);
        }
    }
    float* dst; int cc;
    if (c < NC)          { dst = g_q; cc = c; }
    else if (c < 2 * NC) { dst = g_k; cc = c - NC; }
    else                 { dst = g_v; cc = c - 2 * NC; }
    *(float4*)(dst + (size_t)p * NC + cc) = acc;
}

// ---------------- QK^T + fused square-sums ----------------
__global__ __launch_bounds__(256) void qk_kernel()
{
    int bn = blockIdx.x;
    int split = blockIdx.y;
    const float* qb = g_q + (size_t)bn * CH * HW;
    const float* kb = g_k + (size_t)bn * CH * HW;

    __shared__ float Qs[CH][65];
    __shared__ float Ks[CH][65];

    int t = threadIdx.x;
    int d0 = (t >> 4) * 3;
    int e0 = (t & 15) * 3;

    float acc[3][3];
#pragma unroll
    for (int i = 0; i < 3; i++)
#pragma unroll
        for (int j = 0; j < 3; j++) acc[i][j] = 0.f;
    float qss[3] = {0.f, 0.f, 0.f}, kss[3] = {0.f, 0.f, 0.f};

    for (int chunk = 0; chunk < 32; chunk++) {
        int s0 = split * 2048 + chunk * 64;
#pragma unroll
        for (int i = 0; i < 3; i++) {
            int fidx = t + 256 * i;
            int r = fidx >> 4;
            int c4 = fidx & 15;
            float4 qv = *(const float4*)(qb + (size_t)r * HW + s0 + c4 * 4);
            Qs[r][c4 * 4 + 0] = qv.x; Qs[r][c4 * 4 + 1] = qv.y;
            Qs[r][c4 * 4 + 2] = qv.z; Qs[r][c4 * 4 + 3] = qv.w;
            qss[i] += qv.x * qv.x + qv.y * qv.y + qv.z * qv.z + qv.w * qv.w;
            float4 kv = *(const float4*)(kb + (size_t)r * HW + s0 + c4 * 4);
            Ks[r][c4 * 4 + 0] = kv.x; Ks[r][c4 * 4 + 1] = kv.y;
            Ks[r][c4 * 4 + 2] = kv.z; Ks[r][c4 * 4 + 3] = kv.w;
            kss[i] += kv.x * kv.x + kv.y * kv.y + kv.z * kv.z + kv.w * kv.w;
        }
        __syncthreads();
#pragma unroll 8
        for (int ss = 0; ss < 64; ss++) {
            float q0 = Qs[d0][ss], q1 = Qs[d0 + 1][ss], q2 = Qs[d0 + 2][ss];
            float k0 = Ks[e0][ss], k1 = Ks[e0 + 1][ss], k2 = Ks[e0 + 2][ss];
            acc[0][0] = fmaf(q0, k0, acc[0][0]);
            acc[0][1] = fmaf(q0, k1, acc[0][1]);
            acc[0][2] = fmaf(q0, k2, acc[0][2]);
            acc[1][0] = fmaf(q1, k0, acc[1][0]);
            acc[1][1] = fmaf(q1, k1, acc[1][1]);
            acc[1][2] = fmaf(q1, k2, acc[1][2]);
            acc[2][0] = fmaf(q2, k0, acc[2][0]);
            acc[2][1] = fmaf(q2, k1, acc[2][1]);
            acc[2][2] = fmaf(q2, k2, acc[2][2]);
        }
        __syncthreads();
    }
#pragma unroll
    for (int i = 0; i < 3; i++)
#pragma unroll
        for (int o = 8; o > 0; o >>= 1) {
            qss[i] += __shfl_xor_sync(~0u, qss[i], o);
            kss[i] += __shfl_xor_sync(~0u, kss[i], o);
        }
    if ((t & 15) == 0) {
        int rbase = bn * CH + (t >> 4);
#pragma unroll
        for (int i = 0; i < 3; i++) {
            atomicAdd(&g_ssq_q[rbase + 16 * i], qss[i]);
            atomicAdd(&g_ssq_k[rbase + 16 * i], kss[i]);
        }
    }
#pragma unroll
    for (int i = 0; i < 3; i++)
#pragma unroll
        for (int j = 0; j < 3; j++)
            atomicAdd(&g_attn[bn * CH * CH + (d0 + i) * CH + (e0 + j)], acc[i][j]);
}

// ---------------- softmax with l2-norm scaling + temperature ----------------
__global__ void softmax48_kernel(const float* __restrict__ temp)
{
    int row = blockIdx.x;
    int bn = row / CH;
    int n = bn & (HEADS - 1);
    int l = threadIdx.x;
    float tf = temp[n];
    float iq = rsqrtf(fmaxf(g_ssq_q[row], 1e-12f));
    float* arow = g_attn + (size_t)row * CH;

    float ik0 = rsqrtf(fmaxf(g_ssq_k[bn * CH + l], 1e-12f));
    float v0 = arow[l] * iq * ik0 * tf;
    float v1 = -3.0e38f;
    if (l < 16) {
        float ik1 = rsqrtf(fmaxf(g_ssq_k[bn * CH + l + 32], 1e-12f));
        v1 = arow[l + 32] * iq * ik1 * tf;
    }
    float m = fmaxf(v0, v1);
#pragma unroll
    for (int o = 16; o > 0; o >>= 1) m = fmaxf(m, __shfl_xor_sync(~0u, m, o));
    float e0 = expf(v0 - m);
    float e1 = (l < 16) ? expf(v1 - m) : 0.f;
    float s = e0 + e1;
#pragma unroll
    for (int o = 16; o > 0; o >>= 1) s += __shfl_xor_sync(~0u, s, o);
    float inv = 1.f / s;
    arow[l] = e0 * inv;
    if (l < 16) arow[l + 32] = e1 * inv;
}

// ---------------- out = attn @ V ----------------
__global__ __launch_bounds__(256) void av_kernel()
{
    int bn = blockIdx.x;
    int s2 = blockIdx.y * 256 + threadIdx.x;

    __shared__ float As[CH * CH];
    for (int f = threadIdx.x; f < CH * CH; f += 256) As[f] = g_attn[bn * CH * CH + f];
    __syncthreads();

    const float2* vb = (const float2*)(g_v + (size_t)bn * CH * HW) + s2;
    float2 vr[CH];
#pragma unroll
    for (int e = 0; e < CH; e++) vr[e] = vb[(size_t)e * (HW / 2)];

    float2* ob = (float2*)(g_o + (size_t)bn * CH * HW) + s2;
    for (int d = 0; d < CH; d++) {
        float2 a = make_float2(0.f, 0.f);
#pragma unroll
        for (int e = 0; e < CH; e++) {
            float w = As[d * CH + e];
            a.x = fmaf(w, vr[e].x, a.x);
            a.y = fmaf(w, vr[e].y, a.y);
        }
        ob[(size_t)d * (HW / 2)] = a;
    }
}

// ---------------- launch ----------------
extern "C" void kernel_launch(void* const* d_in, const int* in_sizes, int n_in,
                              void* d_out, int out_size)
{
    const float* x      = (const float*)d_in[0];
    const float* qkv_w  = (const float*)d_in[1];
    const float* dw_w   = (const float*)d_in[2];
    const float* proj_w = (const float*)d_in[3];
    const float* temp   = (const float*)d_in[4];
    float* out = (float*)d_out;

    float *qkv_buf, *o_buf;
    cudaGetSymbolAddress((void**)&qkv_buf, g_qkv);
    cudaGetSymbolAddress((void**)&o_buf, g_o);
    __nv_bfloat16 *wqh, *wql, *wph, *wpl;
    cudaGetSymbolAddress((void**)&wqh, g_wqkv_h);
    cudaGetSymbolAddress((void**)&wql, g_wqkv_l);
    cudaGetSymbolAddress((void**)&wph, g_wproj_h);
    cudaGetSymbolAddress((void**)&wpl, g_wproj_l);

    cudaFuncSetAttribute(gemm_mma_split, cudaFuncAttributeMaxDynamicSharedMemorySize, GEMM_SMEM);

    const int M = NB * HW;

    // 0) weight transpose + bf16 split + zero scratch
    wprep_kernel<<<(C3 * KDIM + 255) / 256, 256>>>(qkv_w, proj_w);

    // 1) qkv = x @ qkv_w
    gemm_mma_split<<<M / 128, 256, GEMM_SMEM>>>(x, wqh, wql, qkv_buf, C3);

    // 2) depthwise 3x3 + split
    dwconv_split_kernel<<<(NB * HW * (C3 / 4)) / 256, 256>>>(dw_w);

    // 3) QK^T + fused square sums
    qk_kernel<<<dim3(BNT, 8), 256>>>();

    // 4) scale + softmax
    softmax48_kernel<<<BNT * CH, 32>>>(temp);

    // 5) out = attn @ V
    av_kernel<<<dim3(BNT, HW / 512), 256>>>();

    // 6) projection
    gemm_mma_split<<<M / 128, 256, GEMM_SMEM>>>(o_buf, wph, wpl, out, NC);
}